// round 1
// baseline (speedup 1.0000x reference)
#include <cuda_runtime.h>
#include <math.h>

#define NB 4
#define NA 256
#define GSZ 12
#define NGR 1728
#define KA 8
#define KG 32
#define NL 4
#define CODE 64
#define HID 128
#define EDGEF 64
#define NGAUSS 20
#define NATOM (NB*NA)          // 1024
#define NGRID (NB*NGR)         // 6912
#define NNODE (NATOM+NGRID)    // 7936
#define MIROWS (2*CODE+EDGEF)  // 192

// ---------------- static device scratch (no allocations allowed) ----------------
__device__ float g_h[2][NNODE*CODE];     // ping-pong node features
__device__ int   g_nbrA[NATOM][KA];
__device__ int   g_nbrG[NGRID][KG];
__device__ float g_Psrc[NATOM*HID];      // h_src @ W1a (atoms only are sources)
__device__ float g_Pdst[NNODE*HID];      // h_dst @ W1b + b1eff
__device__ float g_EW1[NGAUSS*HID];      // eW @ W1c  (per current layer)
__device__ float g_b1eff[HID];           // b1 + eb @ W1c

struct GaussC { float off[NGAUSS]; float coeff[NGAUSS]; };

// ---------------- init: one-hot atoms, zero grid ----------------
__global__ void k_init(const int* __restrict__ atype) {
    int i = blockIdx.x * blockDim.x + threadIdx.x;
    if (i >= NNODE * CODE) return;
    int n = i >> 6, c = i & 63;
    float v = 0.f;
    if (n < NATOM && c == atype[n]) v = 1.f;
    g_h[0][i] = v;
}

// ---------------- atom-atom kNN (8 nearest, no self) ----------------
__global__ void k_knn_atoms(const float* __restrict__ pos) {
    __shared__ float sx[NA], sy[NA], sz[NA];
    int b = blockIdx.x, i = threadIdx.x;
    int gi = b * NA + i;
    sx[i] = pos[gi*3+0]; sy[i] = pos[gi*3+1]; sz[i] = pos[gi*3+2];
    __syncthreads();
    float px = sx[i], py = sy[i], pz = sz[i];
    float bd[KA]; int bi[KA];
#pragma unroll
    for (int q = 0; q < KA; q++) { bd[q] = 1e30f; bi[q] = 0; }
    float wv = 1e30f; int ws = 0;
    for (int j = 0; j < NA; j++) {
        if (j == i) continue;
        float dx = sx[j]-px, dy = sy[j]-py, dz = sz[j]-pz;
        float d2 = dx*dx + dy*dy + dz*dz;
        if (d2 < wv) {
#pragma unroll
            for (int q = 0; q < KA; q++) if (q == ws) { bd[q] = d2; bi[q] = j; }
            wv = -1.0f;
#pragma unroll
            for (int q = 0; q < KA; q++) if (bd[q] > wv) { wv = bd[q]; ws = q; }
        }
    }
#pragma unroll
    for (int q = 0; q < KA; q++) g_nbrA[gi][q] = b * NA + bi[q];
}

// ---------------- grid->atom kNN (32 nearest atoms per grid node) ----------------
__global__ void k_knn_grid(const float* __restrict__ pos) {
    __shared__ float sx[NA], sy[NA], sz[NA];
    int b = blockIdx.x / 27;
    int chunk = blockIdx.x % 27;
    for (int j = threadIdx.x; j < NA; j += 64) {
        int gj = b * NA + j;
        sx[j] = pos[gj*3+0]; sy[j] = pos[gj*3+1]; sz[j] = pos[gj*3+2];
    }
    __syncthreads();
    int g = chunk * 64 + threadIdx.x;           // 0..1727
    int ix = g / (GSZ*GSZ), iy = (g / GSZ) % GSZ, iz = g % GSZ;
    float px = -8.25f + 1.5f * ix;
    float py = -8.25f + 1.5f * iy;
    float pz = -8.25f + 1.5f * iz;
    float bd[KG]; int bi[KG];
#pragma unroll
    for (int q = 0; q < KG; q++) { bd[q] = 1e30f; bi[q] = 0; }
    float wv = 1e30f; int ws = 0;
    for (int j = 0; j < NA; j++) {
        float dx = sx[j]-px, dy = sy[j]-py, dz = sz[j]-pz;
        float d2 = dx*dx + dy*dy + dz*dz;
        if (d2 < wv) {
#pragma unroll
            for (int q = 0; q < KG; q++) if (q == ws) { bd[q] = d2; bi[q] = j; }
            wv = -1.0f;
#pragma unroll
            for (int q = 0; q < KG; q++) if (bd[q] > wv) { wv = bd[q]; ws = q; }
        }
    }
    int row = b * NGR + g;
#pragma unroll
    for (int q = 0; q < KG; q++) g_nbrG[row][q] = b * NA + bi[q];
}

// ---------------- per-layer weight folding: EW1 = eW@W1c, b1eff = b1 + eb@W1c ----------------
__global__ void k_prep(const float* __restrict__ eW, const float* __restrict__ eb,
                       const float* __restrict__ W1, const float* __restrict__ b1) {
    __shared__ float seW[NGAUSS*EDGEF];
    __shared__ float seb[EDGEF];
    int c = threadIdx.x;     // 0..127
    for (int i = c; i < NGAUSS*EDGEF; i += HID) seW[i] = eW[i];
    if (c < EDGEF) seb[c] = eb[c];
    __syncthreads();
    float acc[NGAUSS];
#pragma unroll
    for (int g = 0; g < NGAUSS; g++) acc[g] = 0.f;
    float accb = 0.f;
    for (int e = 0; e < EDGEF; e++) {
        float w = W1[(2*CODE + e) * HID + c];
        accb = fmaf(seb[e], w, accb);
#pragma unroll
        for (int g = 0; g < NGAUSS; g++) acc[g] = fmaf(seW[g*EDGEF + e], w, acc[g]);
    }
#pragma unroll
    for (int g = 0; g < NGAUSS; g++) g_EW1[g*HID + c] = acc[g];
    g_b1eff[c] = b1[c] + accb;
}

// ---------------- per-node projections: Psrc (atoms), Pdst (all) ----------------
__global__ void k_node_pre(const float* __restrict__ W1, int cur) {
    __shared__ float hsh[CODE];
    int c = threadIdx.x;   // 0..127
    for (int n = blockIdx.x; n < NNODE; n += gridDim.x) {
        if (c < CODE) hsh[c] = g_h[cur][n*CODE + c];
        __syncthreads();
        bool atom = n < NATOM;
        float pd = g_b1eff[c];
        float ps = 0.f;
#pragma unroll 4
        for (int k = 0; k < CODE; k++) {
            float hv = hsh[k];
            pd = fmaf(hv, W1[(CODE + k)*HID + c], pd);
            if (atom) ps = fmaf(hv, W1[k*HID + c], ps);
        }
        g_Pdst[n*HID + c] = pd;
        if (atom) g_Psrc[n*HID + c] = ps;
        __syncthreads();
    }
}

// ---------------- fused edge message + aggregate + W2 + residual + LayerNorm ----------------
__global__ void __launch_bounds__(HID)
k_edge(const float* __restrict__ pos, const float* __restrict__ W2,
       const float* __restrict__ b2, const float* __restrict__ lng,
       const float* __restrict__ lnb, GaussC gc, int cur, int last,
       float* __restrict__ out) {
    __shared__ float4 sG4[KG][5];     // gaussians per neighbor, packed
    __shared__ float  sHS[HID];
    __shared__ int    sNbr[KG];
    __shared__ float  sred[4];
    int t = threadIdx.x;              // 0..127

    // per-thread EW1 column in registers (fixed per layer)
    float ew[NGAUSS];
#pragma unroll
    for (int g = 0; g < NGAUSS; g++) ew[g] = g_EW1[g*HID + t];

    for (int q = 0; q < 4; q++) {
        int n = blockIdx.x * 4 + q;
        bool atom = n < NATOM;                 // uniform per block-iteration
        if (last && atom) continue;           // last layer: only grid nodes needed
        int k = atom ? KA : KG;

        if (t < k) {
            float px, py, pz;
            if (atom) {
                px = pos[n*3+0]; py = pos[n*3+1]; pz = pos[n*3+2];
            } else {
                int g = (n - NATOM) % NGR;
                int ix = g/(GSZ*GSZ), iy = (g/GSZ)%GSZ, iz = g%GSZ;
                px = -8.25f + 1.5f*ix; py = -8.25f + 1.5f*iy; pz = -8.25f + 1.5f*iz;
            }
            int j = atom ? g_nbrA[n][t] : g_nbrG[n - NATOM][t];
            sNbr[t] = j;
            float dx = pos[j*3+0]-px, dy = pos[j*3+1]-py, dz = pos[j*3+2]-pz;
            float dist = fminf(sqrtf(dx*dx + dy*dy + dz*dz), 5.0f);
            float gv[NGAUSS];
#pragma unroll
            for (int g = 0; g < NGAUSS; g++) {
                float dd = dist - gc.off[g];
                gv[g] = expf(gc.coeff[g] * dd * dd);
            }
            sG4[t][0] = make_float4(gv[0],  gv[1],  gv[2],  gv[3]);
            sG4[t][1] = make_float4(gv[4],  gv[5],  gv[6],  gv[7]);
            sG4[t][2] = make_float4(gv[8],  gv[9],  gv[10], gv[11]);
            sG4[t][3] = make_float4(gv[12], gv[13], gv[14], gv[15]);
            sG4[t][4] = make_float4(gv[16], gv[17], gv[18], gv[19]);
        }
        __syncthreads();

        // stage 1: hidden_sum over neighbors (per hidden channel t)
        float pd = g_Pdst[n*HID + t];
        float hs = 0.f;
        for (int j = 0; j < k; j++) {
            int src = sNbr[j];
            float a0 = pd + g_Psrc[src*HID + t];
            float a1 = 0.f, a2 = 0.f, a3 = 0.f;
#pragma unroll
            for (int gg = 0; gg < 5; gg++) {
                float4 gq = sG4[j][gg];
                a0 = fmaf(gq.x, ew[gg*4+0], a0);
                a1 = fmaf(gq.y, ew[gg*4+1], a1);
                a2 = fmaf(gq.z, ew[gg*4+2], a2);
                a3 = fmaf(gq.w, ew[gg*4+3], a3);
            }
            hs += fmaxf((a0 + a1) + (a2 + a3), 0.f);
        }
        sHS[t] = hs;
        __syncthreads();

        // stage 2: aggr = mean(hidden) @ W2 + b2 ; residual + LN (threads 0..63)
        float x = 0.f;
        if (t < CODE) {
            float acc = 0.f;
#pragma unroll 4
            for (int c = 0; c < HID; c++) acc = fmaf(sHS[c], W2[c*CODE + t], acc);
            x = g_h[cur][n*CODE + t] + acc * (1.0f / (float)k) + b2[t];
        }
        // mean over 64 (warps 0,1 active for data; all warps run reductions)
        float s = (t < CODE) ? x : 0.f;
#pragma unroll
        for (int o = 16; o; o >>= 1) s += __shfl_xor_sync(0xffffffff, s, o);
        if ((t & 31) == 0 && t < CODE) sred[t >> 5] = s;
        __syncthreads();
        float mu = (sred[0] + sred[1]) * (1.0f / CODE);
        float d = (t < CODE) ? (x - mu) : 0.f;
        float s2 = d * d;
#pragma unroll
        for (int o = 16; o; o >>= 1) s2 += __shfl_xor_sync(0xffffffff, s2, o);
        if ((t & 31) == 0 && t < CODE) sred[2 + (t >> 5)] = s2;
        __syncthreads();
        if (t < CODE) {
            float var = (sred[2] + sred[3]) * (1.0f / CODE);
            float yv = d / sqrtf(var + 1e-5f) * lng[t] + lnb[t];
            if (last) out[(n - NATOM)*CODE + t] = yv;
            else      g_h[cur ^ 1][n*CODE + t] = yv;
        }
        __syncthreads();
    }
}

// ---------------- launch ----------------
extern "C" void kernel_launch(void* const* d_in, const int* in_sizes, int n_in,
                              void* d_out, int out_size) {
    const float* pos    = (const float*)d_in[0];
    const int*   atype  = (const int*)  d_in[1];
    const float* edge_W = (const float*)d_in[3];
    const float* edge_b = (const float*)d_in[4];
    const float* W1     = (const float*)d_in[5];
    const float* b1     = (const float*)d_in[6];
    const float* W2     = (const float*)d_in[7];
    const float* b2     = (const float*)d_in[8];
    const float* lng    = (const float*)d_in[9];
    const float* lnb    = (const float*)d_in[10];
    float* out = (float*)d_out;

    GaussC gc;
    {
        double off[NGAUSS], dd[NGAUSS];
        double hi = log(6.0);   // log(CUT + 1)
        for (int g = 0; g < NGAUSS; g++) off[g] = exp(hi * (double)g / 19.0) - 1.0;
        for (int g = NGAUSS - 1; g >= 1; g--) dd[g] = off[g] - off[g-1];
        dd[0] = dd[1];
        for (int g = 0; g < NGAUSS; g++) {
            gc.off[g]   = (float)off[g];
            gc.coeff[g] = (float)(-0.5 / (dd[g] * dd[g]));
        }
    }

    k_init<<<(NNODE*CODE + 255)/256, 256>>>(atype);
    k_knn_atoms<<<NB, NA>>>(pos);
    k_knn_grid<<<NB*27, 64>>>(pos);

    int cur = 0;
    for (int l = 0; l < NL; l++) {
        k_prep<<<1, HID>>>(edge_W + l*NGAUSS*EDGEF, edge_b + l*EDGEF,
                           W1 + l*MIROWS*HID, b1 + l*HID);
        k_node_pre<<<248, HID>>>(W1 + l*MIROWS*HID, cur);
        k_edge<<<NNODE/4, HID>>>(pos, W2 + l*HID*CODE, b2 + l*CODE,
                                 lng + l*CODE, lnb + l*CODE, gc, cur,
                                 (l == NL-1) ? 1 : 0, out);
        cur ^= 1;
    }
}

// round 2
// speedup vs baseline: 2.4073x; 2.4073x over previous
#include <cuda_runtime.h>
#include <math.h>

typedef unsigned long long u64;

#define NB 4
#define NA 256
#define GSZ 12
#define NGR 1728
#define KA 8
#define KG 32
#define NL 4
#define CODE 64
#define HID 128
#define EDGEF 64
#define NGAUSS 20
#define NATOM (NB*NA)          // 1024
#define NGRID (NB*NGR)         // 6912
#define NNODE (NATOM+NGRID)    // 7936
#define MIROWS (2*CODE+EDGEF)  // 192

#define PD_BLOCKS 256
#define PS_BLOCKS 40
#define EDGE_BLOCKS 740

// ---------------- static device scratch ----------------
__device__ float g_h[2][NNODE*CODE];
__device__ float g_npos[NNODE*3];
__device__ int   g_nbrA[NATOM][KA];
__device__ int   g_nbrG[NGRID][KG];
__device__ float g_Psrc[NATOM*HID];
__device__ float g_Pdst[NNODE*HID];
__device__ float g_EW1[NL][NGAUSS*HID];
__device__ float g_b1eff[NL][HID];
__device__ float4 g_W2q[NL][32*CODE];   // [k4][c] = W2 rows 4k4..4k4+3, col c

struct GaussC { float off[NGAUSS]; float coeff[NGAUSS]; };

// ---------------- f32x2 helpers ----------------
__device__ __forceinline__ void ffma2(u64 &d, u64 a, u64 b) {
    asm("fma.rn.f32x2 %0, %1, %2, %0;" : "+l"(d) : "l"(a), "l"(b));
}
__device__ __forceinline__ u64 add2(u64 a, u64 b) {
    u64 r; asm("add.rn.f32x2 %0, %1, %2;" : "=l"(r) : "l"(a), "l"(b)); return r;
}
__device__ __forceinline__ u64 pk(float x, float y) {
    u64 r; asm("mov.b64 %0, {%1, %2};" : "=l"(r) : "f"(x), "f"(y)); return r;
}
__device__ __forceinline__ float2 upk(u64 v) {
    float2 r; asm("mov.b64 {%0, %1}, %2;" : "=f"(r.x), "=f"(r.y) : "l"(v)); return r;
}

// ---------------- init: one-hot h, node positions ----------------
__global__ void k_init(const int* __restrict__ atype, const float* __restrict__ pos) {
    int i = blockIdx.x * blockDim.x + threadIdx.x;
    if (i < NNODE * CODE) {
        int n = i >> 6, c = i & 63;
        g_h[0][i] = (n < NATOM && c == atype[n]) ? 1.f : 0.f;
    }
    if (i < NNODE) {
        float x, y, z;
        if (i < NATOM) { x = pos[i*3]; y = pos[i*3+1]; z = pos[i*3+2]; }
        else {
            int g = (i - NATOM) % NGR;
            int ix = g / (GSZ*GSZ), iy = (g / GSZ) % GSZ, iz = g % GSZ;
            x = -8.25f + 1.5f*ix; y = -8.25f + 1.5f*iy; z = -8.25f + 1.5f*iz;
        }
        g_npos[i*3] = x; g_npos[i*3+1] = y; g_npos[i*3+2] = z;
    }
}

// ---------------- warp-per-node kNN: atoms (K=8) ----------------
__global__ void __launch_bounds__(128) k_knn_a(const float* __restrict__ pos) {
    __shared__ float sx[NA], sy[NA], sz[NA];
    int t = threadIdx.x, lane = t & 31, w = t >> 5;
    int b = (blockIdx.x * 4) / NA;
    for (int j = t; j < NA; j += 128) {
        int gj = b * NA + j;
        sx[j] = pos[gj*3]; sy[j] = pos[gj*3+1]; sz[j] = pos[gj*3+2];
    }
    __syncthreads();
    int il = (blockIdx.x * 4 + w) % NA;          // node local index
    float px = sx[il], py = sy[il], pz = sz[il];
    float d[8];
#pragma unroll
    for (int q = 0; q < 8; q++) {
        int j = q * 32 + lane;
        float dx = sx[j]-px, dy = sy[j]-py, dz = sz[j]-pz;
        float dd = dx*dx + dy*dy + dz*dz;
        d[q] = (j == il) ? 1e30f : dd;
    }
    int keep = 0;
    for (int r = 0; r < KA; r++) {
        float mv = d[0]; int mq = 0;
#pragma unroll
        for (int q = 1; q < 8; q++) if (d[q] < mv) { mv = d[q]; mq = q; }
        int mj = mq * 32 + lane;
#pragma unroll
        for (int off = 16; off; off >>= 1) {
            float ov = __shfl_xor_sync(0xffffffffu, mv, off);
            int   oj = __shfl_xor_sync(0xffffffffu, mj, off);
            if (ov < mv) { mv = ov; mj = oj; }
        }
        if (lane == r) keep = mj;
        if ((mj & 31) == lane) {
            int q = mj >> 5;
#pragma unroll
            for (int qq = 0; qq < 8; qq++) if (qq == q) d[qq] = 1e30f;
        }
    }
    if (lane < KA) g_nbrA[b * NA + il][lane] = b * NA + keep;
}

// ---------------- warp-per-node kNN: grid (K=32) ----------------
__global__ void __launch_bounds__(128) k_knn_g(const float* __restrict__ pos) {
    __shared__ float sx[NA], sy[NA], sz[NA];
    int t = threadIdx.x, lane = t & 31, w = t >> 5;
    int b = (blockIdx.x * 4) / NGR;
    for (int j = t; j < NA; j += 128) {
        int gj = b * NA + j;
        sx[j] = pos[gj*3]; sy[j] = pos[gj*3+1]; sz[j] = pos[gj*3+2];
    }
    __syncthreads();
    int gl = (blockIdx.x * 4 + w) % NGR;
    int ix = gl / (GSZ*GSZ), iy = (gl / GSZ) % GSZ, iz = gl % GSZ;
    float px = -8.25f + 1.5f*ix, py = -8.25f + 1.5f*iy, pz = -8.25f + 1.5f*iz;
    float d[8];
#pragma unroll
    for (int q = 0; q < 8; q++) {
        int j = q * 32 + lane;
        float dx = sx[j]-px, dy = sy[j]-py, dz = sz[j]-pz;
        d[q] = dx*dx + dy*dy + dz*dz;
    }
    int keep = 0;
    for (int r = 0; r < KG; r++) {
        float mv = d[0]; int mq = 0;
#pragma unroll
        for (int q = 1; q < 8; q++) if (d[q] < mv) { mv = d[q]; mq = q; }
        int mj = mq * 32 + lane;
#pragma unroll
        for (int off = 16; off; off >>= 1) {
            float ov = __shfl_xor_sync(0xffffffffu, mv, off);
            int   oj = __shfl_xor_sync(0xffffffffu, mj, off);
            if (ov < mv) { mv = ov; mj = oj; }
        }
        if (lane == r) keep = mj;
        if ((mj & 31) == lane) {
            int q = mj >> 5;
#pragma unroll
            for (int qq = 0; qq < 8; qq++) if (qq == q) d[qq] = 1e30f;
        }
    }
    g_nbrG[b * NGR + gl][lane] = b * NA + keep;
}

// ---------------- all-layer weight folding (one launch) ----------------
__global__ void k_prep_all(const float* __restrict__ edge_W, const float* __restrict__ edge_b,
                           const float* __restrict__ W1, const float* __restrict__ b1,
                           const float* __restrict__ W2) {
    int bid = blockIdx.x, c = threadIdx.x;   // 128 threads
    if (bid < NL * NGAUSS) {
        int l = bid / NGAUSS, g = bid % NGAUSS;
        __shared__ float se[EDGEF];
        if (c < EDGEF) se[c] = edge_W[(l * NGAUSS + g) * EDGEF + c];
        __syncthreads();
        const float* W1c = W1 + l * MIROWS * HID + 2 * CODE * HID;
        float acc = 0.f;
#pragma unroll
        for (int e = 0; e < EDGEF; e++) acc = fmaf(se[e], W1c[e * HID + c], acc);
        g_EW1[l][g * HID + c] = acc;
    } else if (bid < NL * NGAUSS + NL) {
        int l = bid - NL * NGAUSS;
        __shared__ float se[EDGEF];
        if (c < EDGEF) se[c] = edge_b[l * EDGEF + c];
        __syncthreads();
        const float* W1c = W1 + l * MIROWS * HID + 2 * CODE * HID;
        float acc = b1[l * HID + c];
#pragma unroll
        for (int e = 0; e < EDGEF; e++) acc = fmaf(se[e], W1c[e * HID + c], acc);
        g_b1eff[l][c] = acc;
    } else {
        int l = bid - NL * NGAUSS - NL;
        const float* W2l = W2 + l * HID * CODE;
        for (int idx = c; idx < 32 * CODE; idx += 128) {
            int k4 = idx / CODE, cc = idx % CODE;
            g_W2q[l][idx] = make_float4(W2l[(4*k4+0)*CODE + cc], W2l[(4*k4+1)*CODE + cc],
                                        W2l[(4*k4+2)*CODE + cc], W2l[(4*k4+3)*CODE + cc]);
        }
    }
}

// ---------------- per-node projections (weight-stationary in regs) ----------------
__global__ void __launch_bounds__(128) k_proj(const float* __restrict__ W1, int l, int cur) {
    int c = threadIdx.x;
    bool srcRole = blockIdx.x >= PD_BLOCKS;
    const float* Wb = W1 + (srcRole ? 0 : CODE * HID);
    float w[CODE];
#pragma unroll
    for (int k = 0; k < CODE; k++) w[k] = Wb[k * HID + c];
    float bias = srcRole ? 0.f : g_b1eff[l][c];
    float* dst = srcRole ? g_Psrc : g_Pdst;
    int nCh = (srcRole ? NATOM : NNODE) / 4;
    int b0 = srcRole ? (blockIdx.x - PD_BLOCKS) : blockIdx.x;
    int nBlk = srcRole ? PS_BLOCKS : PD_BLOCKS;
    __shared__ __align__(16) float hsh[4 * CODE];
    const float* hsrc = g_h[cur];
    for (int ch = b0; ch < nCh; ch += nBlk) {
        int n0 = ch * 4;
        hsh[c]       = hsrc[n0 * CODE + c];
        hsh[c + 128] = hsrc[n0 * CODE + 128 + c];
        __syncthreads();
#pragma unroll
        for (int q = 0; q < 4; q++) {
            float acc = bias;
            const float4* h4 = (const float4*)(hsh + q * CODE);
#pragma unroll
            for (int k4 = 0; k4 < 16; k4++) {
                float4 hv = h4[k4];
                acc = fmaf(hv.x, w[4*k4+0], acc);
                acc = fmaf(hv.y, w[4*k4+1], acc);
                acc = fmaf(hv.z, w[4*k4+2], acc);
                acc = fmaf(hv.w, w[4*k4+3], acc);
            }
            dst[(n0 + q) * HID + c] = acc;
        }
        __syncthreads();
    }
}

// ---------------- fused edge kernel: 2 nodes/block, f32x2 packed ----------------
__global__ void __launch_bounds__(128) k_edge(
    const float* __restrict__ b2, const float* __restrict__ lng,
    const float* __restrict__ lnb, GaussC gc, int l, int cur, int last,
    float* __restrict__ out)
{
    __shared__ __align__(16) float4 sW2[32 * CODE];       // 32KB
    __shared__ __align__(16) u64    sG[2][KG][NGAUSS];    // 10KB, (g,g) pairs
    __shared__ int   sNbr[2][KG];
    __shared__ __align__(16) float  sHS[2][HID];
    __shared__ float sred[2][2][2];

    int t = threadIdx.x;
    int half = t >> 6, c = t & 63, lane = t & 31, hw = (t >> 5) & 1;

    for (int i = t; i < 32 * CODE; i += 128) sW2[i] = g_W2q[l][i];

    u64 ew[NGAUSS];
    const u64* ewq = (const u64*)g_EW1[l];
#pragma unroll
    for (int g = 0; g < NGAUSS; g++) ew[g] = ewq[g * 64 + c];

    int nStart = last ? NATOM : 0;
    int nPairs = (NNODE - nStart) >> 1;
    const u64* psrcq = (const u64*)g_Psrc;
    const u64* pdstq = (const u64*)g_Pdst;

    for (int p = blockIdx.x; p < nPairs; p += gridDim.x) {
        int n = nStart + p * 2 + half;
        bool atom = n < NATOM;
        int k = atom ? KA : KG;
        __syncthreads();
        if (c < k) {
            int j = atom ? g_nbrA[n][c] : g_nbrG[n - NATOM][c];
            sNbr[half][c] = j;
            float px = g_npos[n*3], py = g_npos[n*3+1], pz = g_npos[n*3+2];
            float dx = g_npos[j*3]-px, dy = g_npos[j*3+1]-py, dz = g_npos[j*3+2]-pz;
            float dist = fminf(sqrtf(dx*dx + dy*dy + dz*dz), 5.0f);
#pragma unroll
            for (int g = 0; g < NGAUSS; g++) {
                float dd = dist - gc.off[g];
                float gv = expf(gc.coeff[g] * dd * dd);
                sG[half][c][g] = pk(gv, gv);
            }
        }
        __syncthreads();

        // ---- stage 1: hidden sums (channels 2c, 2c+1) ----
        u64 pd = pdstq[n * 64 + c];
        float hs0 = 0.f, hs1 = 0.f;
        for (int j0 = 0; j0 < k; j0 += 8) {
            u64 ps[8];
#pragma unroll
            for (int m = 0; m < 8; m++) ps[m] = psrcq[sNbr[half][j0 + m] * 64 + c];
#pragma unroll
            for (int m = 0; m < 8; m++) {
                u64 a0 = add2(pd, ps[m]);
                u64 a1 = 0ull;
                const u64* gj = sG[half][j0 + m];
#pragma unroll
                for (int g2 = 0; g2 < NGAUSS; g2 += 2) {
                    ulonglong2 gp = *(const ulonglong2*)(gj + g2);
                    ffma2(a0, gp.x, ew[g2]);
                    ffma2(a1, gp.y, ew[g2 + 1]);
                }
                float2 v0 = upk(a0), v1 = upk(a1);
                hs0 += fmaxf(v0.x + v1.x, 0.f);
                hs1 += fmaxf(v0.y + v1.y, 0.f);
            }
        }
        ((float2*)sHS[half])[c] = make_float2(hs0, hs1);
        __syncthreads();

        // ---- stage 2: aggr = mean(hidden) @ W2 + b2 ----
        u64 acc0 = 0ull, acc1 = 0ull;
        const ulonglong2* hq = (const ulonglong2*)sHS[half];
#pragma unroll
        for (int k4 = 0; k4 < 32; k4++) {
            ulonglong2 hv = hq[k4];
            ulonglong2 wv = *(const ulonglong2*)&sW2[k4 * CODE + c];
            ffma2(acc0, hv.x, wv.x);
            ffma2(acc1, hv.y, wv.y);
        }
        float2 a0 = upk(acc0), a1 = upk(acc1);
        float aggr = (a0.x + a0.y + a1.x + a1.y) * (atom ? (1.f/KA) : (1.f/KG));
        float x = g_h[cur][n * CODE + c] + aggr + b2[c];

        // ---- LayerNorm over 64 channels (2 warps per node) ----
        float s = x;
#pragma unroll
        for (int off = 16; off; off >>= 1) s += __shfl_xor_sync(0xffffffffu, s, off);
        if (lane == 0) sred[half][0][hw] = s;
        __syncthreads();
        float mu = (sred[half][0][0] + sred[half][0][1]) * (1.f / CODE);
        float dv = x - mu;
        float s2 = dv * dv;
#pragma unroll
        for (int off = 16; off; off >>= 1) s2 += __shfl_xor_sync(0xffffffffu, s2, off);
        if (lane == 0) sred[half][1][hw] = s2;
        __syncthreads();
        float var = (sred[half][1][0] + sred[half][1][1]) * (1.f / CODE);
        float y = dv * rsqrtf(var + 1e-5f) * lng[c] + lnb[c];
        if (last) out[(n - NATOM) * CODE + c] = y;
        else      g_h[cur ^ 1][n * CODE + c] = y;
    }
}

// ---------------- launch ----------------
extern "C" void kernel_launch(void* const* d_in, const int* in_sizes, int n_in,
                              void* d_out, int out_size) {
    const float* pos    = (const float*)d_in[0];
    const int*   atype  = (const int*)  d_in[1];
    const float* edge_W = (const float*)d_in[3];
    const float* edge_b = (const float*)d_in[4];
    const float* W1     = (const float*)d_in[5];
    const float* b1     = (const float*)d_in[6];
    const float* W2     = (const float*)d_in[7];
    const float* b2     = (const float*)d_in[8];
    const float* lng    = (const float*)d_in[9];
    const float* lnb    = (const float*)d_in[10];
    float* out = (float*)d_out;

    GaussC gc;
    {
        double off[NGAUSS], dd[NGAUSS];
        double hi = log(6.0);
        for (int g = 0; g < NGAUSS; g++) off[g] = exp(hi * (double)g / 19.0) - 1.0;
        for (int g = NGAUSS - 1; g >= 1; g--) dd[g] = off[g] - off[g-1];
        dd[0] = dd[1];
        for (int g = 0; g < NGAUSS; g++) {
            gc.off[g]   = (float)off[g];
            gc.coeff[g] = (float)(-0.5 / (dd[g] * dd[g]));
        }
    }

    k_init<<<(NNODE*CODE + 255)/256, 256>>>(atype, pos);
    k_knn_a<<<NATOM/4, 128>>>(pos);
    k_knn_g<<<NGRID/4, 128>>>(pos);
    k_prep_all<<<NL*NGAUSS + 2*NL, 128>>>(edge_W, edge_b, W1, b1, W2);

    int cur = 0;
    for (int l = 0; l < NL; l++) {
        k_proj<<<PD_BLOCKS + PS_BLOCKS, 128>>>(W1 + l*MIROWS*HID, l, cur);
        k_edge<<<EDGE_BLOCKS, 128>>>(b2 + l*CODE, lng + l*CODE, lnb + l*CODE,
                                     gc, l, cur, (l == NL-1) ? 1 : 0, out);
        cur ^= 1;
    }
}

// round 3
// speedup vs baseline: 2.4561x; 1.0203x over previous
#include <cuda_runtime.h>
#include <math.h>

typedef unsigned long long u64;

#define NB 4
#define NA 256
#define GSZ 12
#define NGR 1728
#define KA 8
#define KG 32
#define NL 4
#define CODE 64
#define HID 128
#define EDGEF 64
#define NGAUSS 20
#define NATOM (NB*NA)          // 1024
#define NGRID (NB*NGR)         // 6912
#define NNODE (NATOM+NGRID)    // 7936
#define MIROWS (2*CODE+EDGEF)  // 192

#define EDGE_BLOCKS 740
#define CLIPBIT (1 << 30)

// ---------------- static device scratch ----------------
__device__ float g_h[2][NNODE*CODE];
__device__ float g_npos[NNODE*3];
__device__ int   g_nbrA[NATOM][KA];
__device__ int   g_nbrG[NGRID][KG];
__device__ float g_Psrc[NATOM*HID];
__device__ float g_EW1[NL][NGAUSS*HID];
__device__ float g_b1eff[NL][HID];
__device__ float g_C[NL][HID];           // gauss(5.0) @ EW1
__device__ float4 g_W2q[NL][32*CODE];    // [k4][c] = W2 rows 4k4..4k4+3, col c

struct GaussC { float off[NGAUSS]; float coeff[NGAUSS]; float g5[NGAUSS]; };

// ---------------- f32x2 helpers ----------------
__device__ __forceinline__ void ffma2(u64 &d, u64 a, u64 b) {
    asm("fma.rn.f32x2 %0, %1, %2, %0;" : "+l"(d) : "l"(a), "l"(b));
}
__device__ __forceinline__ u64 add2(u64 a, u64 b) {
    u64 r; asm("add.rn.f32x2 %0, %1, %2;" : "=l"(r) : "l"(a), "l"(b)); return r;
}
__device__ __forceinline__ u64 pk(float x, float y) {
    u64 r; asm("mov.b64 %0, {%1, %2};" : "=l"(r) : "f"(x), "f"(y)); return r;
}
__device__ __forceinline__ float2 upk(u64 v) {
    float2 r; asm("mov.b64 {%0, %1}, %2;" : "=f"(r.x), "=f"(r.y) : "l"(v)); return r;
}

// ---------------- init ----------------
__global__ void k_init(const int* __restrict__ atype, const float* __restrict__ pos) {
    int i = blockIdx.x * blockDim.x + threadIdx.x;
    if (i < NNODE * CODE) {
        int n = i >> 6, c = i & 63;
        g_h[0][i] = (n < NATOM && c == atype[n]) ? 1.f : 0.f;
    }
    if (i < NNODE) {
        float x, y, z;
        if (i < NATOM) { x = pos[i*3]; y = pos[i*3+1]; z = pos[i*3+2]; }
        else {
            int g = (i - NATOM) % NGR;
            int ix = g / (GSZ*GSZ), iy = (g / GSZ) % GSZ, iz = g % GSZ;
            x = -8.25f + 1.5f*ix; y = -8.25f + 1.5f*iy; z = -8.25f + 1.5f*iz;
        }
        g_npos[i*3] = x; g_npos[i*3+1] = y; g_npos[i*3+2] = z;
    }
}

// ---------------- warp-per-node kNN (stable ties: smaller index wins) ----------------
__global__ void __launch_bounds__(128) k_knn_a(const float* __restrict__ pos) {
    __shared__ float sx[NA], sy[NA], sz[NA];
    int t = threadIdx.x, lane = t & 31, w = t >> 5;
    int b = (blockIdx.x * 4) / NA;
    for (int j = t; j < NA; j += 128) {
        int gj = b * NA + j;
        sx[j] = pos[gj*3]; sy[j] = pos[gj*3+1]; sz[j] = pos[gj*3+2];
    }
    __syncthreads();
    int il = (blockIdx.x * 4 + w) % NA;
    float px = sx[il], py = sy[il], pz = sz[il];
    float d[8];
#pragma unroll
    for (int q = 0; q < 8; q++) {
        int j = q * 32 + lane;
        float dx = sx[j]-px, dy = sy[j]-py, dz = sz[j]-pz;
        float dd = dx*dx + dy*dy + dz*dz;
        d[q] = (j == il) ? 1e30f : dd;
    }
    int keep = 0;
    for (int r = 0; r < KA; r++) {
        float mv = d[0]; int mq = 0;
#pragma unroll
        for (int q = 1; q < 8; q++) if (d[q] < mv) { mv = d[q]; mq = q; }
        int mj = mq * 32 + lane;
#pragma unroll
        for (int off = 16; off; off >>= 1) {
            float ov = __shfl_xor_sync(0xffffffffu, mv, off);
            int   oj = __shfl_xor_sync(0xffffffffu, mj, off);
            if (ov < mv || (ov == mv && oj < mj)) { mv = ov; mj = oj; }
        }
        if (lane == r) keep = mj;
        if ((mj & 31) == lane) {
            int q = mj >> 5;
#pragma unroll
            for (int qq = 0; qq < 8; qq++) if (qq == q) d[qq] = 1e30f;
        }
    }
    if (lane < KA) g_nbrA[b * NA + il][lane] = b * NA + keep;
}

__global__ void __launch_bounds__(128) k_knn_g(const float* __restrict__ pos) {
    __shared__ float sx[NA], sy[NA], sz[NA];
    int t = threadIdx.x, lane = t & 31, w = t >> 5;
    int b = (blockIdx.x * 4) / NGR;
    for (int j = t; j < NA; j += 128) {
        int gj = b * NA + j;
        sx[j] = pos[gj*3]; sy[j] = pos[gj*3+1]; sz[j] = pos[gj*3+2];
    }
    __syncthreads();
    int gl = (blockIdx.x * 4 + w) % NGR;
    int ix = gl / (GSZ*GSZ), iy = (gl / GSZ) % GSZ, iz = gl % GSZ;
    float px = -8.25f + 1.5f*ix, py = -8.25f + 1.5f*iy, pz = -8.25f + 1.5f*iz;
    float d[8];
#pragma unroll
    for (int q = 0; q < 8; q++) {
        int j = q * 32 + lane;
        float dx = sx[j]-px, dy = sy[j]-py, dz = sz[j]-pz;
        d[q] = dx*dx + dy*dy + dz*dz;
    }
    int keep = 0;
    for (int r = 0; r < KG; r++) {
        float mv = d[0]; int mq = 0;
#pragma unroll
        for (int q = 1; q < 8; q++) if (d[q] < mv) { mv = d[q]; mq = q; }
        int mj = mq * 32 + lane;
#pragma unroll
        for (int off = 16; off; off >>= 1) {
            float ov = __shfl_xor_sync(0xffffffffu, mv, off);
            int   oj = __shfl_xor_sync(0xffffffffu, mj, off);
            if (ov < mv || (ov == mv && oj < mj)) { mv = ov; mj = oj; }
        }
        if (lane == r) keep = mj;
        if ((mj & 31) == lane) {
            int q = mj >> 5;
#pragma unroll
            for (int qq = 0; qq < 8; qq++) if (qq == q) d[qq] = 1e30f;
        }
    }
    g_nbrG[b * NGR + gl][lane] = b * NA + keep;
}

// ---------------- all-layer weight folding ----------------
__global__ void k_prep_all(const float* __restrict__ edge_W, const float* __restrict__ edge_b,
                           const float* __restrict__ W1, const float* __restrict__ b1,
                           const float* __restrict__ W2, GaussC gc) {
    int bid = blockIdx.x, c = threadIdx.x;   // 128 threads
    if (bid < NL * NGAUSS) {
        int l = bid / NGAUSS, g = bid % NGAUSS;
        __shared__ float se[EDGEF];
        if (c < EDGEF) se[c] = edge_W[(l * NGAUSS + g) * EDGEF + c];
        __syncthreads();
        const float* W1c = W1 + l * MIROWS * HID + 2 * CODE * HID;
        float acc = 0.f;
#pragma unroll
        for (int e = 0; e < EDGEF; e++) acc = fmaf(se[e], W1c[e * HID + c], acc);
        g_EW1[l][g * HID + c] = acc;
    } else if (bid < NL * NGAUSS + NL) {
        int l = bid - NL * NGAUSS;
        __shared__ float se[EDGEF];
        if (c < EDGEF) se[c] = edge_b[l * EDGEF + c];
        __syncthreads();
        const float* W1c = W1 + l * MIROWS * HID + 2 * CODE * HID;
        float acc = b1[l * HID + c];
#pragma unroll
        for (int e = 0; e < EDGEF; e++) acc = fmaf(se[e], W1c[e * HID + c], acc);
        g_b1eff[l][c] = acc;
    } else if (bid < NL * NGAUSS + 2 * NL) {
        int l = bid - NL * NGAUSS - NL;
        // C = gauss(5.0) @ eW @ W1c
        __shared__ float sE[EDGEF];
        if (c < EDGEF) {
            float acc = 0.f;
#pragma unroll
            for (int g = 0; g < NGAUSS; g++)
                acc = fmaf(gc.g5[g], edge_W[(l * NGAUSS + g) * EDGEF + c], acc);
            sE[c] = acc;
        }
        __syncthreads();
        const float* W1c = W1 + l * MIROWS * HID + 2 * CODE * HID;
        float acc = 0.f;
#pragma unroll
        for (int e = 0; e < EDGEF; e++) acc = fmaf(sE[e], W1c[e * HID + c], acc);
        g_C[l][c] = acc;
    } else {
        int l = bid - NL * NGAUSS - 2 * NL;
        const float* W2l = W2 + l * HID * CODE;
        for (int idx = c; idx < 32 * CODE; idx += 128) {
            int k4 = idx / CODE, cc = idx % CODE;
            g_W2q[l][idx] = make_float4(W2l[(4*k4+0)*CODE + cc], W2l[(4*k4+1)*CODE + cc],
                                        W2l[(4*k4+2)*CODE + cc], W2l[(4*k4+3)*CODE + cc]);
        }
    }
}

// ---------------- Psrc: atoms only, weight-stationary ----------------
__global__ void __launch_bounds__(128) k_psrc(const float* __restrict__ W1, int cur) {
    int c = threadIdx.x;
    float w[CODE];
#pragma unroll
    for (int k = 0; k < CODE; k++) w[k] = W1[k * HID + c];
    __shared__ __align__(16) float hsh[4 * CODE];
    const float* hsrc = g_h[cur];
    for (int ch = blockIdx.x; ch < NATOM / 4; ch += 64) {
        int n0 = ch * 4;
        hsh[c]       = hsrc[n0 * CODE + c];
        hsh[c + 128] = hsrc[n0 * CODE + 128 + c];
        __syncthreads();
#pragma unroll
        for (int q = 0; q < 4; q++) {
            float acc = 0.f;
            const float4* h4 = (const float4*)(hsh + q * CODE);
#pragma unroll
            for (int k4 = 0; k4 < 16; k4++) {
                float4 hv = h4[k4];
                acc = fmaf(hv.x, w[4*k4+0], acc);
                acc = fmaf(hv.y, w[4*k4+1], acc);
                acc = fmaf(hv.z, w[4*k4+2], acc);
                acc = fmaf(hv.w, w[4*k4+3], acc);
            }
            g_Psrc[(n0 + q) * HID + c] = acc;
        }
        __syncthreads();
    }
}

// ---------------- fused: Pdst + edge messages + aggregate + W2 + residual + LN ----------------
__global__ void __launch_bounds__(128, 5) k_edge(
    const float* __restrict__ W1, const float* __restrict__ b2,
    const float* __restrict__ lng, const float* __restrict__ lnb,
    GaussC gc, int l, int cur, int last, float* __restrict__ out)
{
    __shared__ u64   sW1bp[64 * 64];        // 32KB: (k2*64+c)*2 + (k&1)
    __shared__ u64   sG[2][KG][NGAUSS];     // 10KB
    __shared__ u64   sHd[2][64];            // 1KB: (h_k, h_k)
    __shared__ __align__(16) float sHS[2][HID];
    __shared__ int   sNbr[2][KG];
    __shared__ float sred[2][2][2];

    int t = threadIdx.x;
    int half = t >> 6, c = t & 63, lane = t & 31, hw = (t >> 5) & 1;

    // stage weights: W1b (dst block of W1) as channel-pairs
    const float* W1b = W1 + CODE * HID;
    for (int i = t; i < 64 * 64; i += 128) {
        int k = i >> 6, cc = i & 63;
        sW1bp[((k >> 1) * 64 + cc) * 2 + (k & 1)] =
            pk(W1b[k * HID + 2 * cc], W1b[k * HID + 2 * cc + 1]);
    }

    u64 ew[NGAUSS];
    const u64* ewq = (const u64*)g_EW1[l];
#pragma unroll
    for (int g = 0; g < NGAUSS; g++) ew[g] = ewq[g * 64 + c];
    u64 Cp  = ((const u64*)g_C[l])[c];
    u64 b1p = ((const u64*)g_b1eff[l])[c];
    float b2c = b2[c], gmc = lng[c], bbc = lnb[c];

    int nStart = last ? NATOM : 0;
    int nPairs = (NNODE - nStart) >> 1;
    const u64* psrcq = (const u64*)g_Psrc;
    const float* hcur = g_h[cur];
    const ulonglong2* w2q = (const ulonglong2*)g_W2q[l];
    __syncthreads();

    for (int p = blockIdx.x; p < nPairs; p += gridDim.x) {
        int n = nStart + p * 2 + half;
        bool atom = n < NATOM;
        int k = atom ? KA : KG;

        sHd[half][c] = pk(hcur[n * 64 + c], hcur[n * 64 + c]);
        if (c < k) {
            int j = atom ? g_nbrA[n][c] : g_nbrG[n - NATOM][c];
            float px = g_npos[n*3], py = g_npos[n*3+1], pz = g_npos[n*3+2];
            float dx = g_npos[j*3]-px, dy = g_npos[j*3+1]-py, dz = g_npos[j*3+2]-pz;
            float dist = sqrtf(dx*dx + dy*dy + dz*dz);
            if (dist >= 5.0f) {
                sNbr[half][c] = j | CLIPBIT;
            } else {
                sNbr[half][c] = j;
#pragma unroll
                for (int g = 0; g < NGAUSS; g++) {
                    float dd = dist - gc.off[g];
                    float gv = expf(gc.coeff[g] * dd * dd);
                    sG[half][c][g] = pk(gv, gv);
                }
            }
        }
        __syncthreads();

        // ---- Pdst for this node's 2 channels ----
        u64 pd = b1p, pdx = 0ull;
#pragma unroll 8
        for (int k2 = 0; k2 < 32; k2++) {
            ulonglong2 hh = *(const ulonglong2*)&sHd[half][2 * k2];
            ulonglong2 ww = *(const ulonglong2*)&sW1bp[(k2 * 64 + c) * 2];
            ffma2(pd, hh.x, ww.x);
            ffma2(pdx, hh.y, ww.y);
        }
        pd = add2(pd, pdx);

        // ---- stage 1: hidden sums over neighbors ----
        float hs0 = 0.f, hs1 = 0.f;
        for (int j0 = 0; j0 < k; j0 += 8) {
            int nf[8]; u64 ps[8];
#pragma unroll
            for (int m = 0; m < 8; m++) {
                nf[m] = sNbr[half][j0 + m];
                ps[m] = psrcq[(nf[m] & 0xFFFF) * 64 + c];
            }
#pragma unroll
            for (int m = 0; m < 8; m++) {
                if (nf[m] & CLIPBIT) {
                    u64 a = add2(add2(pd, ps[m]), Cp);
                    float2 v = upk(a);
                    hs0 += fmaxf(v.x, 0.f);
                    hs1 += fmaxf(v.y, 0.f);
                } else {
                    u64 a0 = add2(pd, ps[m]);
                    u64 a1 = 0ull;
                    const u64* gj = sG[half][j0 + m];
#pragma unroll
                    for (int g2 = 0; g2 < NGAUSS; g2 += 2) {
                        ulonglong2 gp = *(const ulonglong2*)(gj + g2);
                        ffma2(a0, gp.x, ew[g2]);
                        ffma2(a1, gp.y, ew[g2 + 1]);
                    }
                    float2 v0 = upk(a0), v1 = upk(a1);
                    hs0 += fmaxf(v0.x + v1.x, 0.f);
                    hs1 += fmaxf(v0.y + v1.y, 0.f);
                }
            }
        }
        ((float2*)sHS[half])[c] = make_float2(hs0, hs1);
        __syncthreads();

        // ---- stage 2: aggr = mean(hidden) @ W2 (one output channel c) ----
        u64 acc0 = 0ull, acc1 = 0ull;
        const ulonglong2* hq = (const ulonglong2*)sHS[half];
#pragma unroll 8
        for (int k4 = 0; k4 < 32; k4++) {
            ulonglong2 hv = hq[k4];
            ulonglong2 wv = __ldg(&w2q[k4 * CODE + c]);
            ffma2(acc0, hv.x, wv.x);
            ffma2(acc1, hv.y, wv.y);
        }
        float2 a0 = upk(acc0), a1 = upk(acc1);
        float aggr = (a0.x + a0.y + a1.x + a1.y) * (atom ? (1.f/KA) : (1.f/KG));
        float x = ((const float*)&sHd[half][c])[0] + aggr + b2c;

        // ---- LayerNorm (two-pass, 2 warps per node) ----
        float s = x;
#pragma unroll
        for (int off = 16; off; off >>= 1) s += __shfl_xor_sync(0xffffffffu, s, off);
        if (lane == 0) sred[half][0][hw] = s;
        __syncthreads();
        float mu = (sred[half][0][0] + sred[half][0][1]) * (1.f / CODE);
        float dv = x - mu;
        float s2 = dv * dv;
#pragma unroll
        for (int off = 16; off; off >>= 1) s2 += __shfl_xor_sync(0xffffffffu, s2, off);
        if (lane == 0) sred[half][1][hw] = s2;
        __syncthreads();
        float var = (sred[half][1][0] + sred[half][1][1]) * (1.f / CODE);
        float y = dv * rsqrtf(var + 1e-5f) * gmc + bbc;
        if (last) out[(n - NATOM) * CODE + c] = y;
        else      g_h[cur ^ 1][n * CODE + c] = y;
        __syncthreads();
    }
}

// ---------------- launch ----------------
extern "C" void kernel_launch(void* const* d_in, const int* in_sizes, int n_in,
                              void* d_out, int out_size) {
    const float* pos    = (const float*)d_in[0];
    const int*   atype  = (const int*)  d_in[1];
    const float* edge_W = (const float*)d_in[3];
    const float* edge_b = (const float*)d_in[4];
    const float* W1     = (const float*)d_in[5];
    const float* b1     = (const float*)d_in[6];
    const float* W2     = (const float*)d_in[7];
    const float* b2     = (const float*)d_in[8];
    const float* lng    = (const float*)d_in[9];
    const float* lnb    = (const float*)d_in[10];
    float* out = (float*)d_out;

    GaussC gc;
    {
        double off[NGAUSS], dd[NGAUSS];
        double hi = log(6.0);
        for (int g = 0; g < NGAUSS; g++) off[g] = exp(hi * (double)g / 19.0) - 1.0;
        for (int g = NGAUSS - 1; g >= 1; g--) dd[g] = off[g] - off[g-1];
        dd[0] = dd[1];
        for (int g = 0; g < NGAUSS; g++) {
            gc.off[g]   = (float)off[g];
            gc.coeff[g] = (float)(-0.5 / (dd[g] * dd[g]));
            double d5 = 5.0 - off[g];
            gc.g5[g]  = (float)exp((double)gc.coeff[g] * d5 * d5);
        }
    }

    k_init<<<(NNODE*CODE + 255)/256, 256>>>(atype, pos);
    k_knn_a<<<NATOM/4, 128>>>(pos);
    k_knn_g<<<NGRID/4, 128>>>(pos);
    k_prep_all<<<NL*NGAUSS + 3*NL, 128>>>(edge_W, edge_b, W1, b1, W2, gc);

    int cur = 0;
    for (int l = 0; l < NL; l++) {
        k_psrc<<<64, 128>>>(W1 + l*MIROWS*HID, cur);
        k_edge<<<EDGE_BLOCKS, 128>>>(W1 + l*MIROWS*HID, b2 + l*CODE,
                                     lng + l*CODE, lnb + l*CODE,
                                     gc, l, cur, (l == NL-1) ? 1 : 0, out);
        cur ^= 1;
    }
}

// round 4
// speedup vs baseline: 2.6554x; 1.0811x over previous
#include <cuda_runtime.h>
#include <math.h>

typedef unsigned long long u64;

#define NB 4
#define NA 256
#define GSZ 12
#define NGR 1728
#define KA 8
#define KG 32
#define NL 4
#define CODE 64
#define HID 128
#define EDGEF 64
#define NGAUSS 20
#define NATOM (NB*NA)          // 1024
#define NGRID (NB*NGR)         // 6912
#define NNODE (NATOM+NGRID)    // 7936
#define MIROWS (2*CODE+EDGEF)  // 192

#define PD_BLOCKS 256
#define PS_BLOCKS 40
#define EDGE_BLOCKS 740
#define CLIPBIT (1 << 30)
#define NMASK 0xFFFF
#define NEDGE (NATOM*KA + NGRID*KG)   // 229376

// ---------------- static device scratch ----------------
__device__ float g_h[2][NNODE*CODE];
__device__ float g_npos[NNODE*3];
__device__ int   g_nbrA[NATOM][KA];
__device__ int   g_nbrG[NGRID][KG];
__device__ float4 g_gsA[NATOM*KA*5];    // 20 gaussians per atom edge
__device__ float4 g_gsG[NGRID*KG*5];    // 20 gaussians per grid edge
__device__ float g_Psrc[NATOM*HID];
__device__ float g_Pdst[NNODE*HID];
__device__ float g_EW1[NL][NGAUSS*HID];
__device__ float g_b1eff[NL][HID];
__device__ float g_C[NL][HID];          // gauss(5.0) @ EW1
__device__ float4 g_W2q[NL][32*CODE];

struct GaussC { float off[NGAUSS]; float coeff2[NGAUSS]; float g5[NGAUSS]; };

// ---------------- f32x2 helpers ----------------
__device__ __forceinline__ void ffma2(u64 &d, u64 a, u64 b) {
    asm("fma.rn.f32x2 %0, %1, %2, %0;" : "+l"(d) : "l"(a), "l"(b));
}
__device__ __forceinline__ u64 add2(u64 a, u64 b) {
    u64 r; asm("add.rn.f32x2 %0, %1, %2;" : "=l"(r) : "l"(a), "l"(b)); return r;
}
__device__ __forceinline__ u64 pk(float x, float y) {
    u64 r; asm("mov.b64 %0, {%1, %2};" : "=l"(r) : "f"(x), "f"(y)); return r;
}
__device__ __forceinline__ float2 upk(u64 v) {
    float2 r; asm("mov.b64 {%0, %1}, %2;" : "=f"(r.x), "=f"(r.y) : "l"(v)); return r;
}
__device__ __forceinline__ void barhalf(int id) {
    asm volatile("bar.sync %0, %1;" :: "r"(id), "r"(64) : "memory");
}

// ================= k_setup: init + knn_a + knn_g + prep, one launch =================
__global__ void __launch_bounds__(128) k_setup(
    const float* __restrict__ pos, const int* __restrict__ atype,
    const float* __restrict__ edge_W, const float* __restrict__ edge_b,
    const float* __restrict__ W1, const float* __restrict__ b1,
    const float* __restrict__ W2, GaussC gc)
{
    __shared__ float sx[NA], sy[NA], sz[NA];
    int bid = blockIdx.x, t = threadIdx.x;

    if (bid < 248) {
        // ---- init h0 + npos ----
        for (int i = bid * 128 + t; i < NNODE * CODE; i += 248 * 128) {
            int n = i >> 6, c = i & 63;
            g_h[0][i] = (n < NATOM && c == atype[n]) ? 1.f : 0.f;
        }
        for (int i = bid * 128 + t; i < NNODE; i += 248 * 128) {
            float x, y, z;
            if (i < NATOM) { x = pos[i*3]; y = pos[i*3+1]; z = pos[i*3+2]; }
            else {
                int g = (i - NATOM) % NGR;
                int ix = g / (GSZ*GSZ), iy = (g / GSZ) % GSZ, iz = g % GSZ;
                x = -8.25f + 1.5f*ix; y = -8.25f + 1.5f*iy; z = -8.25f + 1.5f*iz;
            }
            g_npos[i*3] = x; g_npos[i*3+1] = y; g_npos[i*3+2] = z;
        }
    } else if (bid < 248 + 256) {
        // ---- atom kNN (warp per node, stable ties) ----
        int abid = bid - 248;
        int lane = t & 31, w = t >> 5;
        int b = (abid * 4) / NA;
        for (int j = t; j < NA; j += 128) {
            int gj = b * NA + j;
            sx[j] = pos[gj*3]; sy[j] = pos[gj*3+1]; sz[j] = pos[gj*3+2];
        }
        __syncthreads();
        int il = (abid * 4 + w) % NA;
        float px = sx[il], py = sy[il], pz = sz[il];
        float d[8];
#pragma unroll
        for (int q = 0; q < 8; q++) {
            int j = q * 32 + lane;
            float dx = sx[j]-px, dy = sy[j]-py, dz = sz[j]-pz;
            float dd = dx*dx + dy*dy + dz*dz;
            d[q] = (j == il) ? 1e30f : dd;
        }
        int keep = 0;
        for (int r = 0; r < KA; r++) {
            float mv = d[0]; int mq = 0;
#pragma unroll
            for (int q = 1; q < 8; q++) if (d[q] < mv) { mv = d[q]; mq = q; }
            int mj = mq * 32 + lane;
#pragma unroll
            for (int off = 16; off; off >>= 1) {
                float ov = __shfl_xor_sync(0xffffffffu, mv, off);
                int   oj = __shfl_xor_sync(0xffffffffu, mj, off);
                if (ov < mv || (ov == mv && oj < mj)) { mv = ov; mj = oj; }
            }
            if (lane == r) keep = mj;
            if ((mj & 31) == lane) {
                int q = mj >> 5;
#pragma unroll
                for (int qq = 0; qq < 8; qq++) if (qq == q) d[qq] = 1e30f;
            }
        }
        if (lane < KA) g_nbrA[b * NA + il][lane] = b * NA + keep;
    } else if (bid < 248 + 256 + 1728) {
        // ---- grid kNN (warp per node, stable ties) ----
        int gbid = bid - 504;
        int lane = t & 31, w = t >> 5;
        int b = (gbid * 4) / NGR;
        for (int j = t; j < NA; j += 128) {
            int gj = b * NA + j;
            sx[j] = pos[gj*3]; sy[j] = pos[gj*3+1]; sz[j] = pos[gj*3+2];
        }
        __syncthreads();
        int gl = (gbid * 4 + w) % NGR;
        int ix = gl / (GSZ*GSZ), iy = (gl / GSZ) % GSZ, iz = gl % GSZ;
        float px = -8.25f + 1.5f*ix, py = -8.25f + 1.5f*iy, pz = -8.25f + 1.5f*iz;
        float d[8];
#pragma unroll
        for (int q = 0; q < 8; q++) {
            int j = q * 32 + lane;
            float dx = sx[j]-px, dy = sy[j]-py, dz = sz[j]-pz;
            d[q] = dx*dx + dy*dy + dz*dz;
        }
        int keep = 0;
        for (int r = 0; r < KG; r++) {
            float mv = d[0]; int mq = 0;
#pragma unroll
            for (int q = 1; q < 8; q++) if (d[q] < mv) { mv = d[q]; mq = q; }
            int mj = mq * 32 + lane;
#pragma unroll
            for (int off = 16; off; off >>= 1) {
                float ov = __shfl_xor_sync(0xffffffffu, mv, off);
                int   oj = __shfl_xor_sync(0xffffffffu, mj, off);
                if (ov < mv || (ov == mv && oj < mj)) { mv = ov; mj = oj; }
            }
            if (lane == r) keep = mj;
            if ((mj & 31) == lane) {
                int q = mj >> 5;
#pragma unroll
                for (int qq = 0; qq < 8; qq++) if (qq == q) d[qq] = 1e30f;
            }
        }
        g_nbrG[b * NGR + gl][lane] = b * NA + keep;
    } else {
        // ---- weight folding ----
        int pbid = bid - 2232;
        int c = t;
        if (pbid < NL * NGAUSS) {
            int l = pbid / NGAUSS, g = pbid % NGAUSS;
            if (c < EDGEF) sx[c] = edge_W[(l * NGAUSS + g) * EDGEF + c];
            __syncthreads();
            const float* W1c = W1 + l * MIROWS * HID + 2 * CODE * HID;
            float acc = 0.f;
#pragma unroll
            for (int e = 0; e < EDGEF; e++) acc = fmaf(sx[e], W1c[e * HID + c], acc);
            g_EW1[l][g * HID + c] = acc;
        } else if (pbid < NL * NGAUSS + NL) {
            int l = pbid - NL * NGAUSS;
            if (c < EDGEF) sx[c] = edge_b[l * EDGEF + c];
            __syncthreads();
            const float* W1c = W1 + l * MIROWS * HID + 2 * CODE * HID;
            float acc = b1[l * HID + c];
#pragma unroll
            for (int e = 0; e < EDGEF; e++) acc = fmaf(sx[e], W1c[e * HID + c], acc);
            g_b1eff[l][c] = acc;
        } else if (pbid < NL * NGAUSS + 2 * NL) {
            int l = pbid - NL * NGAUSS - NL;
            if (c < EDGEF) {
                float acc = 0.f;
#pragma unroll
                for (int g = 0; g < NGAUSS; g++)
                    acc = fmaf(gc.g5[g], edge_W[(l * NGAUSS + g) * EDGEF + c], acc);
                sx[c] = acc;
            }
            __syncthreads();
            const float* W1c = W1 + l * MIROWS * HID + 2 * CODE * HID;
            float acc = 0.f;
#pragma unroll
            for (int e = 0; e < EDGEF; e++) acc = fmaf(sx[e], W1c[e * HID + c], acc);
            g_C[l][c] = acc;
        } else {
            int l = pbid - NL * NGAUSS - 2 * NL;
            const float* W2l = W2 + l * HID * CODE;
            for (int idx = c; idx < 32 * CODE; idx += 128) {
                int k4 = idx / CODE, cc = idx % CODE;
                g_W2q[l][idx] = make_float4(W2l[(4*k4+0)*CODE + cc], W2l[(4*k4+1)*CODE + cc],
                                            W2l[(4*k4+2)*CODE + cc], W2l[(4*k4+3)*CODE + cc]);
            }
        }
    }
}

// ================= k_gauss: per-edge gaussians + clip flags, once =================
__global__ void __launch_bounds__(256) k_gauss(GaussC gc) {
    int tid = blockIdx.x * 256 + threadIdx.x;
    if (tid >= NEDGE) return;
    int node, nbr;
    int* sp;
    float4* dst;
    if (tid < NATOM * KA) {
        node = tid / KA;
        sp = &g_nbrA[node][tid % KA];
        dst = &g_gsA[tid * 5];
    } else {
        int e = tid - NATOM * KA;
        node = NATOM + e / KG;
        sp = &g_nbrG[e / KG][e % KG];
        dst = &g_gsG[e * 5];
    }
    nbr = *sp;
    float dx = g_npos[nbr*3]   - g_npos[node*3];
    float dy = g_npos[nbr*3+1] - g_npos[node*3+1];
    float dz = g_npos[nbr*3+2] - g_npos[node*3+2];
    float dist = sqrtf(dx*dx + dy*dy + dz*dz);
    if (dist >= 5.0f) { *sp = nbr | CLIPBIT; return; }
    float gv[NGAUSS];
#pragma unroll
    for (int g = 0; g < NGAUSS; g++) {
        float dd = dist - gc.off[g];
        gv[g] = exp2f(gc.coeff2[g] * dd * dd);
    }
    dst[0] = make_float4(gv[0],  gv[1],  gv[2],  gv[3]);
    dst[1] = make_float4(gv[4],  gv[5],  gv[6],  gv[7]);
    dst[2] = make_float4(gv[8],  gv[9],  gv[10], gv[11]);
    dst[3] = make_float4(gv[12], gv[13], gv[14], gv[15]);
    dst[4] = make_float4(gv[16], gv[17], gv[18], gv[19]);
}

// ================= k_proj: Psrc (atoms) + Pdst (all), weight-stationary =================
__global__ void __launch_bounds__(128) k_proj(const float* __restrict__ W1, int l, int cur) {
    int c = threadIdx.x;
    bool srcRole = blockIdx.x >= PD_BLOCKS;
    const float* Wb = W1 + (srcRole ? 0 : CODE * HID);
    float w[CODE];
#pragma unroll
    for (int k = 0; k < CODE; k++) w[k] = Wb[k * HID + c];
    float bias = srcRole ? 0.f : g_b1eff[l][c];
    float* dst = srcRole ? g_Psrc : g_Pdst;
    int nCh = (srcRole ? NATOM : NNODE) / 4;
    int b0 = srcRole ? (blockIdx.x - PD_BLOCKS) : blockIdx.x;
    int nBlk = srcRole ? PS_BLOCKS : PD_BLOCKS;
    __shared__ __align__(16) float hsh[4 * CODE];
    const float* hsrc = g_h[cur];
    for (int ch = b0; ch < nCh; ch += nBlk) {
        int n0 = ch * 4;
        hsh[c]       = hsrc[n0 * CODE + c];
        hsh[c + 128] = hsrc[n0 * CODE + 128 + c];
        __syncthreads();
#pragma unroll
        for (int q = 0; q < 4; q++) {
            float acc = bias;
            const float4* h4 = (const float4*)(hsh + q * CODE);
#pragma unroll
            for (int k4 = 0; k4 < 16; k4++) {
                float4 hv = h4[k4];
                acc = fmaf(hv.x, w[4*k4+0], acc);
                acc = fmaf(hv.y, w[4*k4+1], acc);
                acc = fmaf(hv.z, w[4*k4+2], acc);
                acc = fmaf(hv.w, w[4*k4+3], acc);
            }
            dst[(n0 + q) * HID + c] = acc;
        }
        __syncthreads();
    }
}

// ================= k_edge: stage1 + aggregate + W2 + residual + LN =================
__global__ void __launch_bounds__(128, 5) k_edge(
    const float* __restrict__ b2, const float* __restrict__ lng,
    const float* __restrict__ lnb, int l, int cur, int last,
    float* __restrict__ out)
{
    __shared__ __align__(16) float4 sG[2][KG][5];   // 5KB, un-duplicated gaussians
    __shared__ int    sNbr[2][KG];
    __shared__ __align__(16) float sHS[2][HID];
    __shared__ float2 sred[2][2];

    int t = threadIdx.x;
    int half = t >> 6, c = t & 63, lane = t & 31, hw = (t >> 5) & 1;
    int barid = 1 + half;

    // ew pairs over gaussian axis, per channel: 20 u64 regs
    u64 ewp0[10], ewp1[10];
    const float* ew = g_EW1[l];
#pragma unroll
    for (int i = 0; i < 10; i++) {
        ewp0[i] = pk(ew[(2*i)*HID + 2*c],     ew[(2*i+1)*HID + 2*c]);
        ewp1[i] = pk(ew[(2*i)*HID + 2*c + 1], ew[(2*i+1)*HID + 2*c + 1]);
    }
    u64 Cp = ((const u64*)g_C[l])[c];
    float b2c = b2[c], gmc = lng[c], bbc = lnb[c];

    int nStart = last ? NATOM : 0;
    int nPairs = (NNODE - nStart) >> 1;
    const u64* psrcq = (const u64*)g_Psrc;
    const u64* pdstq = (const u64*)g_Pdst;
    const float* hcur = g_h[cur];
    const ulonglong2* w2q = (const ulonglong2*)g_W2q[l];

    for (int p = blockIdx.x; p < nPairs; p += gridDim.x) {
        int n = nStart + p * 2 + half;
        bool atom = n < NATOM;
        int k = atom ? KA : KG;

        if (c < k) {
            int jr = atom ? g_nbrA[n][c] : g_nbrG[n - NATOM][c];
            sNbr[half][c] = jr;
            if (!(jr & CLIPBIT)) {
                const float4* src = atom ? &g_gsA[(n * KA + c) * 5]
                                         : &g_gsG[((n - NATOM) * KG + c) * 5];
#pragma unroll
                for (int i = 0; i < 5; i++) sG[half][c][i] = src[i];
            }
        }
        float hres = __ldg(&hcur[n * CODE + c]);
        barhalf(barid);                       // (A) sNbr/sG ready

        u64 pd = pdstq[n * 64 + c];
        float hs0 = 0.f, hs1 = 0.f;
        for (int j0 = 0; j0 < k; j0 += 8) {
            int nf[8]; u64 ps[8];
#pragma unroll
            for (int m = 0; m < 8; m++) {
                nf[m] = sNbr[half][j0 + m];
                ps[m] = psrcq[(nf[m] & NMASK) * 64 + c];
            }
#pragma unroll
            for (int m = 0; m < 8; m++) {
                u64 bu = add2(pd, ps[m]);
                float2 b = upk(bu);
                if (nf[m] & CLIPBIT) {
                    float2 Cv = upk(Cp);
                    hs0 += fmaxf(b.x + Cv.x, 0.f);
                    hs1 += fmaxf(b.y + Cv.y, 0.f);
                } else {
                    const ulonglong2* gj = (const ulonglong2*)sG[half][j0 + m];
                    u64 A0 = 0ull, A1 = 0ull, B0 = 0ull, B1 = 0ull;
#pragma unroll
                    for (int i2 = 0; i2 < 5; i2++) {
                        ulonglong2 gp = gj[i2];
                        ffma2(A0, gp.x, ewp0[2*i2]);
                        ffma2(B0, gp.x, ewp1[2*i2]);
                        ffma2(A1, gp.y, ewp0[2*i2+1]);
                        ffma2(B1, gp.y, ewp1[2*i2+1]);
                    }
                    float2 va = upk(add2(A0, A1)), vb = upk(add2(B0, B1));
                    hs0 += fmaxf(b.x + va.x + va.y, 0.f);
                    hs1 += fmaxf(b.y + vb.x + vb.y, 0.f);
                }
            }
        }
        ((float2*)sHS[half])[c] = make_float2(hs0, hs1);
        barhalf(barid);                       // (B) sHS ready

        u64 acc0 = 0ull, acc1 = 0ull;
        const ulonglong2* hq = (const ulonglong2*)sHS[half];
#pragma unroll 8
        for (int k4 = 0; k4 < 32; k4++) {
            ulonglong2 hv = hq[k4];
            ulonglong2 wv = __ldg(&w2q[k4 * CODE + c]);
            ffma2(acc0, hv.x, wv.x);
            ffma2(acc1, hv.y, wv.y);
        }
        float2 a0 = upk(acc0), a1 = upk(acc1);
        float x = hres + (a0.x + a0.y + a1.x + a1.y) * (atom ? (1.f/KA) : (1.f/KG)) + b2c;

        // single-pass LN: sum & sumsq together
        float s1 = x, s2 = x * x;
#pragma unroll
        for (int off = 16; off; off >>= 1) {
            s1 += __shfl_xor_sync(0xffffffffu, s1, off);
            s2 += __shfl_xor_sync(0xffffffffu, s2, off);
        }
        if (lane == 0) sred[half][hw] = make_float2(s1, s2);
        barhalf(barid);                       // (C) sred ready
        float2 ra = sred[half][0], rb = sred[half][1];
        float mu  = (ra.x + rb.x) * (1.f / CODE);
        float var = (ra.y + rb.y) * (1.f / CODE) - mu * mu;
        float y = (x - mu) * rsqrtf(var + 1e-5f) * gmc + bbc;
        if (last) out[(n - NATOM) * CODE + c] = y;
        else      g_h[cur ^ 1][n * CODE + c] = y;
    }
}

// ---------------- launch ----------------
extern "C" void kernel_launch(void* const* d_in, const int* in_sizes, int n_in,
                              void* d_out, int out_size) {
    const float* pos    = (const float*)d_in[0];
    const int*   atype  = (const int*)  d_in[1];
    const float* edge_W = (const float*)d_in[3];
    const float* edge_b = (const float*)d_in[4];
    const float* W1     = (const float*)d_in[5];
    const float* b1     = (const float*)d_in[6];
    const float* W2     = (const float*)d_in[7];
    const float* b2     = (const float*)d_in[8];
    const float* lng    = (const float*)d_in[9];
    const float* lnb    = (const float*)d_in[10];
    float* out = (float*)d_out;

    GaussC gc;
    {
        double off[NGAUSS], dd[NGAUSS];
        double hi = log(6.0);
        for (int g = 0; g < NGAUSS; g++) off[g] = exp(hi * (double)g / 19.0) - 1.0;
        for (int g = NGAUSS - 1; g >= 1; g--) dd[g] = off[g] - off[g-1];
        dd[0] = dd[1];
        for (int g = 0; g < NGAUSS; g++) {
            double coeff = -0.5 / (dd[g] * dd[g]);
            gc.off[g]    = (float)off[g];
            gc.coeff2[g] = (float)(coeff * 1.4426950408889634);  // exp -> exp2
            double d5 = 5.0 - off[g];
            gc.g5[g]   = (float)exp(coeff * d5 * d5);
        }
    }

    k_setup<<<2324, 128>>>(pos, atype, edge_W, edge_b, W1, b1, W2, gc);
    k_gauss<<<(NEDGE + 255) / 256, 256>>>(gc);

    int cur = 0;
    for (int l = 0; l < NL; l++) {
        k_proj<<<PD_BLOCKS + PS_BLOCKS, 128>>>(W1 + l*MIROWS*HID, l, cur);
        k_edge<<<EDGE_BLOCKS, 128>>>(b2 + l*CODE, lng + l*CODE, lnb + l*CODE,
                                     l, cur, (l == NL-1) ? 1 : 0, out);
        cur ^= 1;
    }
}